// round 17
// baseline (speedup 1.0000x reference)
#include <cuda_runtime.h>
#include <cuda_fp16.h>
#include <stdint.h>
#include <math.h>

// Problem dims
#define Ln 512
#define Nn 256
#define DMSA 256
#define DPAIR 128
#define Hh 8
#define Dd 32
#define HD 256
#define NL (Nn*Ln)          // 131072
#define NDIM 8192           // (n,d) contraction dim
#define SCALING 0.17677669529663689f
#define EPSC 1e-5f

typedef __half hf;

// ----------------------------------------------------------------------------
// Scratch (device globals). Aliasing:
//   g_bufA = msa_n  then  v^T     g_bufB = q  then  o
__device__ __align__(16) hf g_bufA[33554432];
__device__ __align__(16) hf g_bufB[33554432];
__device__ __align__(16) hf g_k[33554432];     // [h][l][nd]
__device__ __align__(16) hf g_v[33554432];     // [h][l][nd]
__device__ __align__(16) hf g_p[2097152];      // [h][q][k]
__device__ __align__(16) hf g_wt[327680];      // [1280][256]: 0..1023 wq|wk|wv|wg ^T, 1024..1279 w_out^T
__device__ float g_gate[33554432];             // [r=(n,l)][h*32+d]
__device__ float g_attn[2097152];              // [h][q][k]
__device__ float g_bias[2097152];              // [q][k][h]

// ----------------------------------------------------------------------------
__device__ __forceinline__ uint32_t s2u(const void* p){
    uint32_t a;
    asm("{ .reg .u64 t; cvta.to.shared.u64 t, %1; cvt.u32.u64 %0, t; }" : "=r"(a) : "l"(p));
    return a;
}
#define CP16(sa, gp) \
    asm volatile("cp.async.cg.shared.global [%0], [%1], 16;" :: "r"(sa), "l"(gp))
#define CPCOMMIT() asm volatile("cp.async.commit_group;" ::: "memory")
#define CPWAIT(n)  asm volatile("cp.async.wait_group %0;" :: "n"(n) : "memory")

__device__ __forceinline__ void ldsm4(uint32_t a, uint32_t r[4]){
    asm volatile("ldmatrix.sync.aligned.m8n8.x4.shared.b16 {%0,%1,%2,%3}, [%4];"
                 : "=r"(r[0]), "=r"(r[1]), "=r"(r[2]), "=r"(r[3]) : "r"(a));
}
__device__ __forceinline__ void mma16816(float c[4], const uint32_t a[4],
                                         uint32_t b0, uint32_t b1){
    asm volatile("mma.sync.aligned.m16n8k16.row.col.f32.f16.f16.f32 "
                 "{%0,%1,%2,%3}, {%4,%5,%6,%7}, {%8,%9}, {%0,%1,%2,%3};"
                 : "+f"(c[0]), "+f"(c[1]), "+f"(c[2]), "+f"(c[3])
                 : "r"(a[0]), "r"(a[1]), "r"(a[2]), "r"(a[3]), "r"(b0), "r"(b1));
}
__device__ __forceinline__ float fixf(float v){
    if (isnan(v)) return 0.f;
    if (isinf(v)) return v > 0.f ? 3.4028234663852886e38f : -3.4028234663852886e38f;
    return v;
}

// ----------------------------------------------------------------------------
// LayerNorm msa -> bufA (fp16)
__global__ void k_ln_msa(const float* __restrict__ msa,
                         const float* __restrict__ g,
                         const float* __restrict__ b){
    int warp = threadIdx.x >> 5, lane = threadIdx.x & 31;
    size_t row = (size_t)blockIdx.x * 8 + warp;
    const float* x = msa + row * DMSA;
    float v[8]; float s = 0.f;
    #pragma unroll
    for (int i = 0; i < 8; i++){ float t = fixf(x[lane + i*32]); v[i] = t; s += t; }
    #pragma unroll
    for (int o = 16; o; o >>= 1) s += __shfl_xor_sync(0xffffffffu, s, o);
    float mu = s * (1.f/256.f);
    float q = 0.f;
    #pragma unroll
    for (int i = 0; i < 8; i++){ float d0 = v[i] - mu; q += d0*d0; }
    #pragma unroll
    for (int o = 16; o; o >>= 1) q += __shfl_xor_sync(0xffffffffu, q, o);
    float rs = rsqrtf(q * (1.f/256.f) + EPSC);
    #pragma unroll
    for (int i = 0; i < 8; i++){
        int c = lane + i*32;
        g_bufA[row*DMSA + c] = __float2half_rn((v[i] - mu) * rs * g[c] + b[c]);
    }
}

// Weight transpose: g_wt[row=(z*256+j)][k] = W_z[k][j]
__global__ void k_conv_w(const float* __restrict__ wq, const float* __restrict__ wk,
                         const float* __restrict__ wv, const float* __restrict__ wg,
                         const float* __restrict__ wo){
    int row = blockIdx.x, kk = threadIdx.x;
    int z = row >> 8, j = row & 255;
    const float* src = (z==0)?wq:(z==1)?wk:(z==2)?wv:(z==3)?wg:wo;
    g_wt[(size_t)row*256 + kk] = __float2half_rn(src[kk*256 + j]);
}

// LayerNorm pair + bias GEMV
__global__ void k_pair_bias(const float* __restrict__ pair,
                            const float* __restrict__ g,
                            const float* __restrict__ b,
                            const float* __restrict__ wb){
    __shared__ float swb[Hh*DPAIR];
    for (int i = threadIdx.x; i < Hh*DPAIR; i += blockDim.x){
        int h = i / DPAIR, c = i % DPAIR;
        swb[i] = wb[c*Hh + h];
    }
    __syncthreads();
    int warp = threadIdx.x >> 5, lane = threadIdx.x & 31;
    size_t row = (size_t)blockIdx.x * 8 + warp;
    const float* x = pair + row * DPAIR;
    float v[4]; float s = 0.f;
    #pragma unroll
    for (int i = 0; i < 4; i++){ float t = fixf(x[lane + i*32]); v[i] = t; s += t; }
    #pragma unroll
    for (int o = 16; o; o >>= 1) s += __shfl_xor_sync(0xffffffffu, s, o);
    float mu = s * (1.f/128.f);
    float q = 0.f;
    #pragma unroll
    for (int i = 0; i < 4; i++){ float d0 = v[i] - mu; q += d0*d0; }
    #pragma unroll
    for (int o = 16; o; o >>= 1) q += __shfl_xor_sync(0xffffffffu, q, o);
    float rs = rsqrtf(q * (1.f/128.f) + EPSC);
    float acc[8] = {};
    #pragma unroll
    for (int i = 0; i < 4; i++){
        int c = lane + i*32;
        float pn = (v[i] - mu) * rs * g[c] + b[c];
        #pragma unroll
        for (int h = 0; h < 8; h++) acc[h] += pn * swb[h*DPAIR + c];
    }
    #pragma unroll
    for (int h = 0; h < 8; h++)
        #pragma unroll
        for (int o = 16; o; o >>= 1) acc[h] += __shfl_xor_sync(0xffffffffu, acc[h], o);
    float outv = 0.f;
    #pragma unroll
    for (int h = 0; h < 8; h++) if (lane == h) outv = acc[h];
    if (lane < 8) g_bias[row*Hh + lane] = outv;
}

// Transpose V: [h][l][nd] -> [h][nd][l] into bufA
__global__ void k_transpose_v(){
    __shared__ hf tile[32][33];
    int head = blockIdx.z;
    const hf* src = g_v + (size_t)head * Ln * NDIM;
    hf* dst = g_bufA + (size_t)head * NDIM * Ln;
    int nd0 = blockIdx.x * 32, l0 = blockIdx.y * 32;
    #pragma unroll
    for (int yy = 0; yy < 4; yy++)
        tile[threadIdx.y + yy*8][threadIdx.x] =
            src[(size_t)(l0 + threadIdx.y + yy*8) * NDIM + nd0 + threadIdx.x];
    __syncthreads();
    #pragma unroll
    for (int yy = 0; yy < 4; yy++)
        dst[(size_t)(nd0 + threadIdx.y + yy*8) * Ln + l0 + threadIdx.x] =
            tile[threadIdx.x][threadIdx.y + yy*8];
}

// Softmax over k with bias + mask; writes P as fp16
__global__ void k_softmax(const int* __restrict__ mask){
    int h = blockIdx.x >> 9, q = blockIdx.x & (Ln-1);
    const float* row = g_attn + ((size_t)h*Ln + q)*Ln;
    bool padq = (mask[q] == 0);
    int t = threadIdx.x;
    int k0 = t, k1 = t + 256;
    float v0 = (padq || mask[k0] == 0) ? -1e9f : row[k0] + g_bias[((size_t)q*Ln + k0)*Hh + h];
    float v1 = (padq || mask[k1] == 0) ? -1e9f : row[k1] + g_bias[((size_t)q*Ln + k1)*Hh + h];
    __shared__ float red[256];
    red[t] = fmaxf(v0, v1); __syncthreads();
    for (int s = 128; s > 0; s >>= 1){ if (t < s) red[t] = fmaxf(red[t], red[t+s]); __syncthreads(); }
    float m = red[0]; __syncthreads();
    float e0 = expf(v0 - m), e1 = expf(v1 - m);
    red[t] = e0 + e1; __syncthreads();
    for (int s = 128; s > 0; s >>= 1){ if (t < s) red[t] += red[t+s]; __syncthreads(); }
    float inv = 1.f / red[0];
    size_t base = ((size_t)h*Ln + q)*Ln;
    g_p[base + k0] = __float2half_rn(e0*inv);
    g_p[base + k1] = __float2half_rn(e1*inv);
}

// ----------------------------------------------------------------------------
// Warp-MMA GEMM. MODE: 0=QKVG, 1=attn logits, 2=AV, 3=out-proj
// D[BM=128, BN] = A[M,K] @ B[N,K]^T, fp16 K-major operands, fp32 accum.
// 8 warps: 4(M) x 2(N), warp tile 32 x (BN/2).  BK=64, double-buffered cp.async.
// Hot-loop addressing fully strength-reduced: persistent global pointers with
// constant strides; ping-pong unrolled mainloop so buffer offsets are literals.
// SMEM row stride 72 halves (144B, 16B-aligned; conflict-free ldmatrix).
#define RS   72
#define AELE (128*RS)

template<int MODE, int BN>
__global__ __launch_bounds__(256, (BN==64) ? 4 : 2)
void k_mma(const int* __restrict__ mask,
           const float* __restrict__ bg,
           const float* __restrict__ bout,
           float* __restrict__ outp){
    constexpr int BELE = BN*RS;
    constexpr int BUFE = AELE + BELE;
    constexpr uint32_t BUFB = (uint32_t)BUFE*2;
    constexpr int NJ   = BN/32;      // 16-row B groups per warp tile
    constexpr int NI   = BN/16;      // 8-col output groups per warp tile
    constexpr int NBT  = BN/32;      // B staging CP16s per thread
    extern __shared__ hf smem[];
    uint32_t sb = s2u(smem);
    int tid = threadIdx.x, wid = tid >> 5, lid = tid & 31;
    int wm = wid & 3, wn = wid >> 2;
    int h = blockIdx.z;
    int m0 = blockIdx.y * 128, n0 = blockIdx.x * BN;
    const int K   = (MODE==1) ? NDIM : (MODE==2) ? Ln : 256;
    const int nit = K / 64;          // even for all modes (4 / 128 / 8 / 4)

    const hf *A, *B; int lda = 0, ldb = 0;
    if (MODE == 0){
        A = g_bufA; lda = 256;
        B = g_wt;   ldb = 256;
    } else if (MODE == 1){
        size_t o = (size_t)h * Ln * NDIM;
        A = g_bufB + o; lda = NDIM;
        B = g_k + o;    ldb = NDIM;
    } else if (MODE == 2){
        A = g_p + (size_t)h * Ln * Ln; lda = Ln;
        B = g_bufA + (size_t)h * NDIM * Ln; ldb = Ln;
    } else {
        A = g_bufB; lda = 0;
        B = g_wt + 1024*256; ldb = 256;
    }

    // ---- persistent staging pointers (advance by constant stride per K-step)
    int base_r = tid >> 3, cc = tid & 7;
    const hf* pA[4];
    const hf* pB[NBT];
    ptrdiff_t strideA;
    if (MODE == 3){
        strideA = (ptrdiff_t)2 * Ln * NDIM;   // hh advances by 2 per K-step
        #pragma unroll
        for (int t = 0; t < 4; t++){
            int row = m0 + base_r + t*32;
            int n = row >> 9, l = row & (Ln-1);
            pA[t] = A + ((size_t)((cc >> 2)*Ln + l))*NDIM + (n << 5) + (cc & 3)*8;
        }
    } else {
        strideA = 64;
        #pragma unroll
        for (int t = 0; t < 4; t++)
            pA[t] = A + (size_t)(m0 + base_r + t*32)*lda + cc*8;
    }
    #pragma unroll
    for (int t = 0; t < NBT; t++)
        pB[t] = B + (size_t)(n0 + base_r + t*32)*ldb + cc*8;
    uint32_t soA = sb + 2*(base_r*RS + cc*8);
    uint32_t soB = sb + 2*(AELE + base_r*RS + cc*8);

    auto issue = [&](uint32_t bo){
        #pragma unroll
        for (int t = 0; t < 4; t++){
            CP16(soA + bo + t*(32*RS*2), pA[t]);
            pA[t] += strideA;
        }
        #pragma unroll
        for (int t = 0; t < NBT; t++){
            CP16(soB + bo + t*(32*RS*2), pB[t]);
            pB[t] += 64;
        }
        CPCOMMIT();
    };

    float acc[2][NI][4] = {};
    int lrow = lid & 15, lch = lid >> 4;
    uint32_t aw = sb + 2*((wm*32 + lrow)*RS + lch*8);
    uint32_t bw = sb + 2*(AELE + (wn*(BN/2) + lrow)*RS + lch*8);

    auto compute = [&](uint32_t bo){
        #pragma unroll
        for (int kk = 0; kk < 4; kk++){
            uint32_t ah[2][4], bh[NJ][4];
            #pragma unroll
            for (int mi = 0; mi < 2; mi++)
                ldsm4(aw + bo + (mi*16*RS + kk*16)*2, ah[mi]);
            #pragma unroll
            for (int nj = 0; nj < NJ; nj++)
                ldsm4(bw + bo + (nj*16*RS + kk*16)*2, bh[nj]);
            #pragma unroll
            for (int mi = 0; mi < 2; mi++)
                #pragma unroll
                for (int ni = 0; ni < NI; ni++){
                    int nj = ni >> 1, sel = ni & 1;
                    mma16816(acc[mi][ni], ah[mi], bh[nj][sel], bh[nj][2+sel]);
                }
        }
    };

    // ---- ping-pong mainloop (pairs; literal buffer offsets)
    issue(0);
    #pragma unroll 1
    for (int it = 0; it < nit; it += 2){
        issue(BUFB);
        CPWAIT(1); __syncthreads();
        compute(0);
        __syncthreads();
        if (it + 2 < nit){
            issue(0);
            CPWAIT(1); __syncthreads();
            compute(BUFB);
            __syncthreads();
        } else {
            CPWAIT(0); __syncthreads();
            compute(BUFB);
        }
    }

    // epilogue (packed pair stores; cols (gcol, gcol+1) adjacent)
    int lr = lid >> 2, lc = (lid & 3)*2;
    #pragma unroll
    for (int mi = 0; mi < 2; mi++){
        #pragma unroll
        for (int ni = 0; ni < NI; ni++){
            int gcol = n0 + wn*(BN/2) + ni*8 + lc;
            #pragma unroll
            for (int half = 0; half < 2; half++){
                int row = m0 + wm*32 + mi*16 + lr + half*8;
                float v0 = acc[mi][ni][half*2 + 0];
                float v1 = acc[mi][ni][half*2 + 1];
                if (MODE == 0){
                    int z = gcol >> 8, j = gcol & 255;
                    int l = row & (Ln-1), n = row >> 9;
                    bool pad = (mask[l] == 0);
                    if (z == 3){
                        float2 gv;
                        gv.x = 1.f/(1.f + expf(-(v0 + bg[j])));
                        gv.y = 1.f/(1.f + expf(-(v1 + bg[j+1])));
                        *(float2*)&g_gate[(size_t)row*HD + j] = gv;
                    } else {
                        if (pad){ v0 = 0.f; v1 = 0.f; }
                        else if (z == 1){ v0 *= SCALING; v1 *= SCALING; }
                        int hh = j >> 5, d = j & 31;
                        size_t idx = ((size_t)(hh*Ln + l))*NDIM + (n << 5) + d;
                        __half2 hv = __floats2half2_rn(v0, v1);
                        if (z == 0)      *(__half2*)&g_bufB[idx] = hv;
                        else if (z == 1) *(__half2*)&g_k[idx] = hv;
                        else             *(__half2*)&g_v[idx] = hv;
                    }
                } else if (MODE == 1){
                    float2 fv; fv.x = v0; fv.y = v1;
                    *(float2*)&g_attn[((size_t)(h*Ln + row))*Ln + gcol] = fv;
                } else if (MODE == 2){
                    int n = gcol >> 5, d = gcol & 31;
                    float2 gt = *(const float2*)&g_gate[((size_t)(n*Ln + row))*HD + h*32 + d];
                    *(__half2*)&g_bufB[((size_t)(h*Ln + row))*NDIM + gcol] =
                        __floats2half2_rn(v0*gt.x, v1*gt.y);
                } else {
                    int l = row & (Ln-1);
                    bool pad = (mask[l] == 0);
                    float2 ov;
                    ov.x = pad ? 0.f : (v0 + bout[gcol]);
                    ov.y = pad ? 0.f : (v1 + bout[gcol+1]);
                    *(float2*)&outp[(size_t)row*HD + gcol] = ov;
                }
            }
        }
    }
}

// ----------------------------------------------------------------------------
extern "C" void kernel_launch(void* const* d_in, const int* in_sizes, int n_in,
                              void* d_out, int out_size){
    const float* msa      = (const float*)d_in[0];
    const float* pair     = (const float*)d_in[1];
    const float* ln_msa_g = (const float*)d_in[2];
    const float* ln_msa_b = (const float*)d_in[3];
    const float* ln_pr_g  = (const float*)d_in[4];
    const float* ln_pr_b  = (const float*)d_in[5];
    const float* w_q      = (const float*)d_in[6];
    const float* w_k      = (const float*)d_in[7];
    const float* w_v      = (const float*)d_in[8];
    const float* w_b      = (const float*)d_in[9];
    const float* w_g      = (const float*)d_in[10];
    const float* b_g      = (const float*)d_in[11];
    const float* w_out    = (const float*)d_in[12];
    const float* b_out    = (const float*)d_in[13];
    const int*   mask     = (const int*)  d_in[14];
    float* out = (float*)d_out;

    const int SM64  = 2*(AELE + 64*RS)*2;    // 55296
    const int SM128 = 2*(AELE + 128*RS)*2;   // 73728
    cudaFuncSetAttribute(k_mma<0,128>, cudaFuncAttributeMaxDynamicSharedMemorySize, SM128);
    cudaFuncSetAttribute(k_mma<1,64>,  cudaFuncAttributeMaxDynamicSharedMemorySize, SM64);
    cudaFuncSetAttribute(k_mma<2,128>, cudaFuncAttributeMaxDynamicSharedMemorySize, SM128);
    cudaFuncSetAttribute(k_mma<3,128>, cudaFuncAttributeMaxDynamicSharedMemorySize, SM128);

    k_ln_msa   <<<NL/8, 256>>>(msa, ln_msa_g, ln_msa_b);
    k_conv_w   <<<1280, 256>>>(w_q, w_k, w_v, w_g, w_out);
    k_pair_bias<<<(Ln*Ln)/8, 256>>>(pair, ln_pr_g, ln_pr_b, w_b);
    k_mma<0,128><<<dim3(8, 1024, 1), 256, SM128>>>(mask, b_g, b_out, out);
    k_transpose_v<<<dim3(NDIM/32, Ln/32, 8), dim3(32, 8)>>>();
    k_mma<1,64> <<<dim3(8, 4, 8),    256, SM64>>> (mask, b_g, b_out, out);
    k_softmax  <<<Hh*Ln, 256>>>(mask);
    k_mma<2,128><<<dim3(64, 4, 8),   256, SM128>>>(mask, b_g, b_out, out);
    k_mma<3,128><<<dim3(2, 1024, 1), 256, SM128>>>(mask, b_g, b_out, out);
}